// round 8
// baseline (speedup 1.0000x reference)
#include <cuda_runtime.h>

#define B 32
#define M 32
#define C 1024
#define R 28
#define INV_R2 (1.0f / (R * R))

#define IMGS_PER_BLK 8
#define ROWS_PER_BLK (IMGS_PER_BLK * R)          // 224
#define F4_PER_BLK (ROWS_PER_BLK * R / 4)        // 1568
#define THREADS 224
#define F4_PER_THREAD (F4_PER_BLK / THREADS)     // 7
#define BLKS_PER_B (C / IMGS_PER_BLK)            // 128
#define NBLKS (B * C / IMGS_PER_BLK)             // 4096
#define ENTRIES_PER_BLK 7                        // col entries per block
#define CNT_TARGET (ENTRIES_PER_BLK * BLKS_PER_B)  // 896

// Scratch + sync state (allocation-free rule: __device__ globals)
__device__ float g_col[B * M * R];   // column sums of Masks: (B, M, R)
__device__ int   g_cnt[B];           // per-batch completion counters

// Tiny kernel: reset counters each launch/replay (kernels only — no memset node)
__global__ void zero_cnt_kernel() {
    if (threadIdx.x < B) g_cnt[threadIdx.x] = 0;
}

// ---------------------------------------------------------------------------
// Single fused kernel.
//  Phase A (overlapped with F loads): each block computes its 7 col entries
//    (entries [blk*7, blk*7+7) -> all of col[b] is produced by b's own
//    128-block group), publishes via st -> threadfence -> atomicAdd(cnt[b]).
//  Phase B: proven R3 core — 7 coalesced LDG.128 (MLP=7) -> f4 hsum ->
//    scalar partials in smem -> segmented rowsum.
//  Phase C: wait cnt[b]==896 (almost always already true: producers run at
//    block start, consumers at block end), stage col_s, einsum tail.
// Deadlock-free: every block produces BEFORE waiting; 128-block groups are
// contiguous bids << ~740 resident blocks, so complete resident groups
// always retire and free slots for any missing group-mates.
// ---------------------------------------------------------------------------
__global__ void fused_all_kernel(const float* __restrict__ F,
                                 const float* __restrict__ Mk,
                                 float* __restrict__ out) {
    __shared__ float partial[F4_PER_BLK];        // 1568 floats
    __shared__ float rowsum[ROWS_PER_BLK];       // 224 floats
    __shared__ float col_s[M * R];               // 896 floats
    __shared__ float sm_mask[ENTRIES_PER_BLK * R]; // 196 floats

    const int tid = threadIdx.x;
    const int blk = blockIdx.x;
    const int b   = blk / BLKS_PER_B;

    // --- F load batch first: 7 coalesced LDG.128, all in flight (MLP=7) ---
    const float4* src = reinterpret_cast<const float4*>(F) + (size_t)blk * F4_PER_BLK;
    float4 v[F4_PER_THREAD];
#pragma unroll
    for (int k = 0; k < F4_PER_THREAD; k++) v[k] = __ldcs(src + k * THREADS + tid);

    // --- Mask slice load (1 scalar/thread, overlaps the F loads) ---
    // t = i*7 + q: consecutive threads -> consecutive addresses (j varies).
    if (tid < ENTRIES_PER_BLK * R) {
        int q = tid % ENTRIES_PER_BLK;          // local entry
        int i = tid / ENTRIES_PER_BLK;          // mask row
        int e = blk * ENTRIES_PER_BLK + q;      // global (bm, j) entry
        sm_mask[tid] = __ldcs(Mk + (size_t)(e / R) * (R * R) + i * R + (e % R));
    }

    // --- f4 horizontal sums -> scalar partials (stride-1 STS) ---
#pragma unroll
    for (int k = 0; k < F4_PER_THREAD; k++)
        partial[k * THREADS + tid] = (v[k].x + v[k].y) + (v[k].z + v[k].w);
    __syncthreads();

    // --- Publish this block's 7 col entries (release) ---
    if (tid < ENTRIES_PER_BLK) {
        float s = 0.0f;
#pragma unroll
        for (int i = 0; i < R; i++) s += sm_mask[i * ENTRIES_PER_BLK + tid];
        g_col[blk * ENTRIES_PER_BLK + tid] = s;
        __threadfence();
        atomicAdd(&g_cnt[b], 1);
    }

    // --- Segmented row sum: row t = partial[7t..7t+6] (bank permutation) ---
    {
        float s = 0.0f;
#pragma unroll
        for (int k = 0; k < F4_PER_THREAD; k++) s += partial[tid * F4_PER_THREAD + k];
        rowsum[tid] = s;
    }
    __syncthreads();

    // --- Wait for col[b] complete (acquire), then stage it ---
    if (tid == 0) {
        while (atomicAdd(&g_cnt[b], 0) < CNT_TARGET) __nanosleep(64);
        __threadfence();
    }
    __syncthreads();
    {
        const float* cp = g_col + b * (M * R);
#pragma unroll
        for (int k = 0; k < 4; k++)
            col_s[k * THREADS + tid] = __ldcg(cp + k * THREADS + tid);
    }
    __syncthreads();

    // --- Einsum tail: 256 outputs = 32 m x 8 c_local ---
    const int c0 = (blk % BLKS_PER_B) * IMGS_PER_BLK;
    for (int o = tid; o < M * IMGS_PER_BLK; o += THREADS) {
        int m  = o / IMGS_PER_BLK;
        int cl = o % IMGS_PER_BLK;
        float acc = 0.0f;
#pragma unroll
        for (int r = 0; r < R; r++)
            acc += col_s[m * R + r] * rowsum[cl * R + r];
        out[((size_t)b * M + m) * C + c0 + cl] = acc * INV_R2;
    }
}

extern "C" void kernel_launch(void* const* d_in, const int* in_sizes, int n_in,
                              void* d_out, int out_size) {
    const float* F  = (const float*)d_in[0];  // (B, C, R, R)
    const float* Mk = (const float*)d_in[1];  // (B, M, R, R)
    float* out = (float*)d_out;               // (B, M, C)

    zero_cnt_kernel<<<1, 32>>>();
    fused_all_kernel<<<NBLKS, THREADS>>>(F, Mk, out);
}

// round 9
// speedup vs baseline: 1.6739x; 1.6739x over previous
#include <cuda_runtime.h>

#define B 32
#define M 32
#define C 1024
#define R 28
#define INV_R2 (1.0f / (R * R))

#define IMGS_PER_BLK 8
#define ROWS_PER_BLK (IMGS_PER_BLK * R)          // 224
#define F4_PER_BLK (ROWS_PER_BLK * R / 4)        // 1568
#define THREADS 224
#define F4_PER_THREAD (F4_PER_BLK / THREADS)     // 7
#define BLKS_PER_B (C / IMGS_PER_BLK)            // 128

// Scratch (allocation-free rule: __device__ global)
__device__ float g_col[B * M * R];   // column sums of Masks: (B, M, R)

// ---------------------------------------------------------------------------
// Kernel 1 (R6 version — measured best): col[b,m,j] = sum_i Masks[b,m,i,j].
// One thread per (b,m,j) = 28672 threads / 112 blocks, __ldcs streaming,
// 28 independent stride-112B loads (MLP=28), coalesced across j.
// ---------------------------------------------------------------------------
__global__ void reduce_M_kernel(const float* __restrict__ Mk) {
    int tid = blockIdx.x * blockDim.x + threadIdx.x;
    if (tid >= B * M * R) return;
    int j  = tid % R;
    int bm = tid / R;
    const float* p = Mk + (size_t)bm * R * R + j;
    float s = 0.0f;
#pragma unroll
    for (int i = 0; i < R; i++) s += __ldcs(p + i * R);
    g_col[tid] = s;
}

// ---------------------------------------------------------------------------
// Kernel 2: EXACT R3 core (the only 20.4us config) with one reorder:
// the 7-LDG.128 F batch is issued BEFORE the col_s staging loads.
// No launch_bounds, no __ldcs — ptxas' natural 49-reg allocation keeps all
// 7 loads batched (MLP=7); 5 blocks/SM was empirically sufficient.
// ---------------------------------------------------------------------------
__global__ void fused_rowsum_einsum_kernel(const float* __restrict__ F,
                                           float* __restrict__ out) {
    __shared__ float partial[F4_PER_BLK];     // 1568 floats = 6.3 KB
    __shared__ float rowsum[ROWS_PER_BLK];    // 224 floats: [c_local*28 + i]
    __shared__ float col_s[M * R];            // 896 floats: [m*28 + r]

    const int tid = threadIdx.x;
    const int blk = blockIdx.x;
    const int b   = blk / BLKS_PER_B;

    // F load batch first: 7 coalesced LDG.128, all in flight (MLP=7).
    const float4* src = reinterpret_cast<const float4*>(F) + (size_t)blk * F4_PER_BLK;
    float4 v[F4_PER_THREAD];
#pragma unroll
    for (int k = 0; k < F4_PER_THREAD; k++) v[k] = src[k * THREADS + tid];

    // Stage col[b] while the F batch flies (L2-hot: 128 blocks share it).
    {
        const float* cp = g_col + b * (M * R);
#pragma unroll
        for (int k = 0; k < 4; k++)
            col_s[k * THREADS + tid] = cp[k * THREADS + tid];
    }

    // f4 horizontal sums -> scalar partials (stride-1 STS: conflict-free).
#pragma unroll
    for (int k = 0; k < F4_PER_THREAD; k++)
        partial[k * THREADS + tid] = (v[k].x + v[k].y) + (v[k].z + v[k].w);
    __syncthreads();

    // Segmented row sum: row t = partial[7t..7t+6]; 7 coprime to 32 ->
    // per-phase bank permutation -> conflict-free.
    {
        float s = 0.0f;
#pragma unroll
        for (int k = 0; k < F4_PER_THREAD; k++) s += partial[tid * F4_PER_THREAD + k];
        rowsum[tid] = s;
    }
    __syncthreads();

    // Einsum tail: 256 outputs = 32 m x 8 c_local.
    const int c0 = (blk % BLKS_PER_B) * IMGS_PER_BLK;
    for (int o = tid; o < M * IMGS_PER_BLK; o += THREADS) {
        int m  = o / IMGS_PER_BLK;
        int cl = o % IMGS_PER_BLK;
        float acc = 0.0f;
#pragma unroll
        for (int r = 0; r < R; r++)
            acc += col_s[m * R + r] * rowsum[cl * R + r];
        out[((size_t)b * M + m) * C + c0 + cl] = acc * INV_R2;
    }
}

extern "C" void kernel_launch(void* const* d_in, const int* in_sizes, int n_in,
                              void* d_out, int out_size) {
    const float* F  = (const float*)d_in[0];  // (B, C, R, R)
    const float* Mk = (const float*)d_in[1];  // (B, M, R, R)
    float* out = (float*)d_out;               // (B, M, C)

    {
        int n = B * M * R;  // 28672
        reduce_M_kernel<<<(n + 255) / 256, 256>>>(Mk);
    }
    {
        int nblks = (B * C) / IMGS_PER_BLK;   // 4096
        fused_rowsum_einsum_kernel<<<nblks, THREADS>>>(F, out);
    }
}